// round 5
// baseline (speedup 1.0000x reference)
#include <cuda_runtime.h>

#define N_P 100000
#define N_A 50000
#define E_C 1600000
#define E_W 800000
#define IND 768
#define H   128
#define HH  (128*128)

typedef unsigned long long u64;

// ---------------- scratch (device globals; no allocation) ----------------
__device__ float g_hp[(size_t)N_P * H];
__device__ float g_ha[(size_t)N_A * H];
__device__ float g_zp[(size_t)N_P * H];
__device__ float g_za[(size_t)N_A * H];
__device__ float g_aggc[(size_t)N_P * H];
__device__ float g_aggw[(size_t)N_P * H];
__device__ float g_aggr[(size_t)N_A * H];
__device__ float g_Wc[2 * HH];   // 0.5*Wl[l,0]
__device__ float g_Ww[2 * HH];   // 0.5*Wl[l,1]
__device__ float g_Wrp[2 * HH];  // 0.5*(Wr[l,0]+Wr[l,1])
__device__ float g_bp[2 * H];    // 0.5*(bl[l,0]+bl[l,1])
__device__ int g_cptr[N_P + 1], g_cidx[E_C];
__device__ int g_wptr[N_P + 1], g_widx[E_W];
__device__ int g_rptr[N_A + 1], g_ridx[E_W];
__device__ int g_tmp[N_P + 1];

// ---------------- packed fp32x2 helpers ----------------
__device__ __forceinline__ u64 ffma2(u64 a, u64 b, u64 c) {
    u64 d;
    asm("fma.rn.f32x2 %0, %1, %2, %3;" : "=l"(d) : "l"(a), "l"(b), "l"(c));
    return d;
}
__device__ __forceinline__ float lo32(u64 v) {
    return __uint_as_float((unsigned)(v & 0xffffffffull));
}
__device__ __forceinline__ float hi32(u64 v) {
    return __uint_as_float((unsigned)(v >> 32));
}

// ---------------- weight prep ----------------
__global__ void prep_weights(const float* __restrict__ Wl,
                             const float* __restrict__ bl,
                             const float* __restrict__ Wr) {
    int i = blockIdx.x * blockDim.x + threadIdx.x;
    if (i < HH) {
        #pragma unroll
        for (int l = 0; l < 2; l++) {
            g_Wc[l * HH + i]  = 0.5f * Wl[(l * 3 + 0) * HH + i];
            g_Ww[l * HH + i]  = 0.5f * Wl[(l * 3 + 1) * HH + i];
            g_Wrp[l * HH + i] = 0.5f * (Wr[(l * 3 + 0) * HH + i] + Wr[(l * 3 + 1) * HH + i]);
        }
    }
    if (i < H) {
        #pragma unroll
        for (int l = 0; l < 2; l++)
            g_bp[l * H + i] = 0.5f * (bl[(l * 3 + 0) * H + i] + bl[(l * 3 + 1) * H + i]);
    }
}

// ---------------- CSR build ----------------
__global__ void zero_int(int* __restrict__ p, int n) {
    int i = blockIdx.x * blockDim.x + threadIdx.x;
    if (i < n) p[i] = 0;
}

__global__ void count_k(const int* __restrict__ dst, int* __restrict__ cnt, int n) {
    int i = blockIdx.x * blockDim.x + threadIdx.x;
    if (i < n) atomicAdd(&cnt[dst[i]], 1);
}

__global__ void scan_excl(const int* __restrict__ cnt, int* __restrict__ ptr, int n) {
    __shared__ int ss[1024];
    int tid = threadIdx.x;
    int C = (n + 1023) >> 10;
    int start = tid * C;
    int s = 0;
    for (int i = 0; i < C; i++) {
        int p = start + i;
        if (p < n) s += cnt[p];
    }
    ss[tid] = s;
    __syncthreads();
    for (int off = 1; off < 1024; off <<= 1) {
        int v = (tid >= off) ? ss[tid - off] : 0;
        __syncthreads();
        ss[tid] += v;
        __syncthreads();
    }
    int run = (tid > 0) ? ss[tid - 1] : 0;
    for (int i = 0; i < C; i++) {
        int p = start + i;
        if (p <= n) {
            ptr[p] = run;
            if (p < n) run += cnt[p];
        }
    }
}

__global__ void fill_k(const int* __restrict__ src, const int* __restrict__ dst,
                       const int* __restrict__ ptr, int* __restrict__ tmp,
                       int* __restrict__ cidx, int n) {
    int i = blockIdx.x * blockDim.x + threadIdx.x;
    if (i < n) {
        int d = dst[i];
        int p = atomicAdd(&tmp[d], 1);
        cidx[ptr[d] + p] = src[i];
    }
}

// ---------------- mean aggregation: one warp per destination node ----------------
__global__ void agg_mean(const float* __restrict__ feat, const int* __restrict__ ptr,
                         const int* __restrict__ idx, float* __restrict__ out, int n) {
    int w = (blockIdx.x * blockDim.x + threadIdx.x) >> 5;
    int lane = threadIdx.x & 31;
    if (w >= n) return;
    int beg = ptr[w], end = ptr[w + 1];
    float ax = 0.f, ay = 0.f, az = 0.f, aw = 0.f;
    int e = beg;
    for (; e + 4 <= end; e += 4) {
        int s0 = idx[e], s1 = idx[e + 1], s2 = idx[e + 2], s3 = idx[e + 3];
        float4 v0 = ((const float4*)(feat + (size_t)s0 * H))[lane];
        float4 v1 = ((const float4*)(feat + (size_t)s1 * H))[lane];
        float4 v2 = ((const float4*)(feat + (size_t)s2 * H))[lane];
        float4 v3 = ((const float4*)(feat + (size_t)s3 * H))[lane];
        ax += (v0.x + v1.x) + (v2.x + v3.x);
        ay += (v0.y + v1.y) + (v2.y + v3.y);
        az += (v0.z + v1.z) + (v2.z + v3.z);
        aw += (v0.w + v1.w) + (v2.w + v3.w);
    }
    for (; e < end; e++) {
        int s0 = idx[e];
        float4 v0 = ((const float4*)(feat + (size_t)s0 * H))[lane];
        ax += v0.x; ay += v0.y; az += v0.z; aw += v0.w;
    }
    int c = end - beg;
    float inv = 1.0f / (float)(c > 1 ? c : 1);
    float4 r;
    r.x = ax * inv; r.y = ay * inv; r.z = az * inv; r.w = aw * inv;
    ((float4*)(out + (size_t)w * H))[lane] = r;
}

// ---------------- fused multi-input GEMM, FFMA2 (packed f32x2) ----------------
// out[M,128] = EPI( sum_m A_m[M,KD] @ W_m[KD,128] + bias )
// EPI 0: LayerNorm (lng,lnb) then ReLU    (projection)
// EPI 1: ReLU                             (SAGE layer 1)
// EPI 2: ReLU then += res                 (SAGE layer 2 + residual -> d_out)
//
// Tile: 64 rows x 128 cols, 256 threads. Thread (tx,ty): cols tx+32i (i<4),
// rows packed in pairs: (2ty+16rr, 2ty+16rr+1), rr<4. Accumulators are
// packed f32x2 over the row pair -> 16 FFMA2 per (kk, m).
// AsT: k-major A tile, stride 66 (bank-clean, 8B-aligned pairs).
// Wsd: W tile with each value duplicated (w_c at 2c and 2c+1) so the {w,w}
// operand is one LDS.64.
template <int NMAT, int KD, int EPI, int KT>
__global__ __launch_bounds__(256) void gemm_k(
    const float* __restrict__ A0, const float* __restrict__ A1, const float* __restrict__ A2,
    const float* __restrict__ W0, const float* __restrict__ W1, const float* __restrict__ W2,
    const float* __restrict__ bias, const float* __restrict__ lng, const float* __restrict__ lnb,
    const float* __restrict__ res, float* __restrict__ out, int M) {
    __shared__ float AsT[NMAT][KT][66];
    __shared__ float Wsd[NMAT][KT][256];
    const float* Aall[3] = {A0, A1, A2};
    const float* Wall[3] = {W0, W1, W2};
    int t = threadIdx.x;
    int tx = t & 31, ty = t >> 5;
    int row0 = blockIdx.x * 64;

    u64 acc2[4][4];
    #pragma unroll
    for (int r = 0; r < 4; r++)
        #pragma unroll
        for (int i = 0; i < 4; i++) acc2[r][i] = 0ull;

    const int QPR = KT / 4;            // float4 quads per row of the A tile
    #pragma unroll 1
    for (int k0 = 0; k0 < KD; k0 += KT) {
        // ---- stage A tiles (k-major) ----
        {
            int rq = t / QPR, kq = t % QPR;   // rq: row in tile, kq: quad in k
            if (rq < 64) {
                int gr = row0 + rq;
                #pragma unroll
                for (int m = 0; m < NMAT; m++) {
                    float4 v = make_float4(0.f, 0.f, 0.f, 0.f);
                    if (gr < M)
                        v = *(const float4*)(Aall[m] + (size_t)gr * KD + k0 + 4 * kq);
                    AsT[m][4 * kq + 0][rq] = v.x;
                    AsT[m][4 * kq + 1][rq] = v.y;
                    AsT[m][4 * kq + 2][rq] = v.z;
                    AsT[m][4 * kq + 3][rq] = v.w;
                }
            }
        }
        // ---- stage W tiles (duplicated) ----
        {
            int c4 = t & 31;                  // quad of 4 cols
            #pragma unroll
            for (int kb = 0; kb < KT; kb += 8) {
                int k = kb + (t >> 5);
                #pragma unroll
                for (int m = 0; m < NMAT; m++) {
                    float4 v = *(const float4*)(Wall[m] + (size_t)(k0 + k) * H + 4 * c4);
                    float4 d0 = make_float4(v.x, v.x, v.y, v.y);
                    float4 d1 = make_float4(v.z, v.z, v.w, v.w);
                    *(float4*)&Wsd[m][k][8 * c4]     = d0;
                    *(float4*)&Wsd[m][k][8 * c4 + 4] = d1;
                }
            }
        }
        __syncthreads();
        #pragma unroll 4
        for (int kk = 0; kk < KT; kk++) {
            #pragma unroll
            for (int m = 0; m < NMAT; m++) {
                u64 a2[4], w2[4];
                #pragma unroll
                for (int r = 0; r < 4; r++)
                    a2[r] = *(const u64*)&AsT[m][kk][2 * ty + 16 * r];
                #pragma unroll
                for (int i = 0; i < 4; i++)
                    w2[i] = *(const u64*)&Wsd[m][kk][2 * tx + 64 * i];
                #pragma unroll
                for (int r = 0; r < 4; r++)
                    #pragma unroll
                    for (int i = 0; i < 4; i++)
                        acc2[r][i] = ffma2(a2[r], w2[i], acc2[r][i]);
            }
        }
        __syncthreads();
    }

    // ---- epilogue ----
    float be[4], gg[4], bb[4];
    #pragma unroll
    for (int i = 0; i < 4; i++) {
        int c = tx + 32 * i;
        be[i] = bias[c];
        if (EPI == 0) { gg[i] = lng[c]; bb[i] = lnb[c]; }
    }
    #pragma unroll
    for (int rr = 0; rr < 4; rr++) {
        int rl = row0 + 2 * ty + 16 * rr;     // uniform across the warp
        #pragma unroll
        for (int half = 0; half < 2; half++) {
            int gr = rl + half;
            if (gr >= M) continue;
            float v[4];
            #pragma unroll
            for (int i = 0; i < 4; i++)
                v[i] = (half ? hi32(acc2[rr][i]) : lo32(acc2[rr][i])) + be[i];
            if (EPI == 0) {
                float s = v[0] + v[1] + v[2] + v[3];
                #pragma unroll
                for (int o = 16; o > 0; o >>= 1) s += __shfl_xor_sync(0xffffffffu, s, o);
                float mu = s * (1.0f / 128.0f);
                float q = 0.f;
                #pragma unroll
                for (int i = 0; i < 4; i++) { float d = v[i] - mu; q += d * d; }
                #pragma unroll
                for (int o = 16; o > 0; o >>= 1) q += __shfl_xor_sync(0xffffffffu, q, o);
                float rstd = rsqrtf(q * (1.0f / 128.0f) + 1e-5f);
                #pragma unroll
                for (int i = 0; i < 4; i++) {
                    float y = (v[i] - mu) * rstd * gg[i] + bb[i];
                    v[i] = fmaxf(y, 0.f);
                }
            } else {
                #pragma unroll
                for (int i = 0; i < 4; i++) v[i] = fmaxf(v[i], 0.f);
                if (EPI == 2) {
                    #pragma unroll
                    for (int i = 0; i < 4; i++)
                        v[i] += res[(size_t)gr * H + tx + 32 * i];
                }
            }
            #pragma unroll
            for (int i = 0; i < 4; i++)
                out[(size_t)gr * H + tx + 32 * i] = v[i];
        }
    }
}

// ---------------- launch ----------------
extern "C" void kernel_launch(void* const* d_in, const int* in_sizes, int n_in,
                              void* d_out, int out_size) {
    const float* x_paper   = (const float*)d_in[0];
    const float* x_author  = (const float*)d_in[1];
    const float* pw_paper  = (const float*)d_in[2];
    const float* pb_paper  = (const float*)d_in[3];
    const float* lng_paper = (const float*)d_in[4];
    const float* lnb_paper = (const float*)d_in[5];
    const float* pw_author  = (const float*)d_in[6];
    const float* pb_author  = (const float*)d_in[7];
    const float* lng_author = (const float*)d_in[8];
    const float* lnb_author = (const float*)d_in[9];
    const float* Wl = (const float*)d_in[10];
    const float* bl = (const float*)d_in[11];
    const float* Wr = (const float*)d_in[12];
    const int* cs = (const int*)d_in[13];
    const int* cd = (const int*)d_in[14];
    const int* ws = (const int*)d_in[15];
    const int* wd = (const int*)d_in[16];
    const int* rs = (const int*)d_in[17];
    const int* rd = (const int*)d_in[18];
    float* out = (float*)d_out;

    float *hp, *ha, *zp, *za, *aggc, *aggw, *aggr, *Wc, *Ww2, *Wrp, *bp;
    int *cptr, *cidx, *wptr, *widx, *rptr, *ridx, *tmp;
    cudaGetSymbolAddress((void**)&hp, g_hp);
    cudaGetSymbolAddress((void**)&ha, g_ha);
    cudaGetSymbolAddress((void**)&zp, g_zp);
    cudaGetSymbolAddress((void**)&za, g_za);
    cudaGetSymbolAddress((void**)&aggc, g_aggc);
    cudaGetSymbolAddress((void**)&aggw, g_aggw);
    cudaGetSymbolAddress((void**)&aggr, g_aggr);
    cudaGetSymbolAddress((void**)&Wc, g_Wc);
    cudaGetSymbolAddress((void**)&Ww2, g_Ww);
    cudaGetSymbolAddress((void**)&Wrp, g_Wrp);
    cudaGetSymbolAddress((void**)&bp, g_bp);
    cudaGetSymbolAddress((void**)&cptr, g_cptr);
    cudaGetSymbolAddress((void**)&cidx, g_cidx);
    cudaGetSymbolAddress((void**)&wptr, g_wptr);
    cudaGetSymbolAddress((void**)&widx, g_widx);
    cudaGetSymbolAddress((void**)&rptr, g_rptr);
    cudaGetSymbolAddress((void**)&ridx, g_ridx);
    cudaGetSymbolAddress((void**)&tmp, g_tmp);

    prep_weights<<<(HH + 255) / 256, 256>>>(Wl, bl, Wr);

    // per-type projection: Linear -> LayerNorm -> ReLU
    gemm_k<1, IND, 0, 16><<<(N_P + 63) / 64, 256>>>(
        x_paper, nullptr, nullptr, pw_paper, nullptr, nullptr,
        pb_paper, lng_paper, lnb_paper, nullptr, hp, N_P);
    gemm_k<1, IND, 0, 16><<<(N_A + 63) / 64, 256>>>(
        x_author, nullptr, nullptr, pw_author, nullptr, nullptr,
        pb_author, lng_author, lnb_author, nullptr, ha, N_A);

    // CSR build (shared by both layers)
    auto build = [&](const int* s, const int* d, int nn, int ne, int* ptr, int* ci) {
        zero_int<<<(nn + 255) / 256, 256>>>(tmp, nn);
        count_k<<<(ne + 255) / 256, 256>>>(d, tmp, ne);
        scan_excl<<<1, 1024>>>(tmp, ptr, nn);
        zero_int<<<(nn + 255) / 256, 256>>>(tmp, nn);
        fill_k<<<(ne + 255) / 256, 256>>>(s, d, ptr, tmp, ci, ne);
    };
    build(cs, cd, N_P, E_C, cptr, cidx);
    build(ws, wd, N_P, E_W, wptr, widx);
    build(rs, rd, N_A, E_W, rptr, ridx);

    // ---- layer 1 ----
    agg_mean<<<(N_P + 7) / 8, 256>>>(hp, cptr, cidx, aggc, N_P);
    agg_mean<<<(N_P + 7) / 8, 256>>>(ha, wptr, widx, aggw, N_P);
    agg_mean<<<(N_A + 7) / 8, 256>>>(hp, rptr, ridx, aggr, N_A);
    gemm_k<3, H, 1, 8><<<(N_P + 63) / 64, 256>>>(
        aggc, aggw, hp, Wc, Ww2, Wrp,
        bp, nullptr, nullptr, nullptr, zp, N_P);
    gemm_k<2, H, 1, 16><<<(N_A + 63) / 64, 256>>>(
        aggr, ha, nullptr, Wl + 2 * HH, Wr + 2 * HH, nullptr,
        bl + 2 * H, nullptr, nullptr, nullptr, za, N_A);

    // ---- layer 2 (epilogue fuses residual, writes d_out) ----
    agg_mean<<<(N_P + 7) / 8, 256>>>(zp, cptr, cidx, aggc, N_P);
    agg_mean<<<(N_P + 7) / 8, 256>>>(za, wptr, widx, aggw, N_P);
    agg_mean<<<(N_A + 7) / 8, 256>>>(zp, rptr, ridx, aggr, N_A);
    gemm_k<3, H, 2, 8><<<(N_P + 63) / 64, 256>>>(
        aggc, aggw, zp, Wc + HH, Ww2 + HH, Wrp + HH,
        bp + H, nullptr, nullptr, hp, out, N_P);
    gemm_k<2, H, 2, 16><<<(N_A + 63) / 64, 256>>>(
        aggr, za, nullptr, Wl + 5 * HH, Wr + 5 * HH, nullptr,
        bl + 5 * H, nullptr, nullptr, ha, out + (size_t)N_P * H, N_A);

    (void)in_sizes; (void)n_in; (void)out_size;
}

// round 9
// speedup vs baseline: 1.8573x; 1.8573x over previous
#include <cuda_runtime.h>
#include <cuda_bf16.h>
#include <cstdint>

#define N_P 100000
#define N_A 50000
#define E_C 1600000
#define E_W 800000
#define IND 768
#define H   128
#define HH  (128*128)

// ---------------- scratch (device globals; no allocation) ----------------
__device__ float g_hp[(size_t)N_P * H];
__device__ float g_ha[(size_t)N_A * H];
__device__ float g_zp[(size_t)N_P * H];
__device__ float g_za[(size_t)N_A * H];
__device__ float g_aggc[(size_t)N_P * H];
__device__ float g_aggw[(size_t)N_P * H];
__device__ float g_aggr[(size_t)N_A * H];
__device__ float g_bp[2 * H];    // 0.5*(bl[l,0]+bl[l,1])
// transposed + bf16-split weights: [N=128 rows][K cols]
__device__ __align__(16) __nv_bfloat16 g_wPh[128 * IND], g_wPl[128 * IND];   // paper proj
__device__ __align__(16) __nv_bfloat16 g_wAh[128 * IND], g_wAl[128 * IND];   // author proj
__device__ __align__(16) __nv_bfloat16 g_wLPh[2][128 * 384], g_wLPl[2][128 * 384]; // paper layer (K=384)
__device__ __align__(16) __nv_bfloat16 g_wLAh[2][128 * 256], g_wLAl[2][128 * 256]; // author layer (K=256)
__device__ int g_cptr[N_P + 1], g_cidx[E_C];
__device__ int g_wptr[N_P + 1], g_widx[E_W];
__device__ int g_rptr[N_A + 1], g_ridx[E_W];
__device__ int g_tmp[N_P + 1];

// ---------------- helpers ----------------
__device__ __forceinline__ uint32_t s2u(const void* p) {
    uint32_t a;
    asm("{ .reg .u64 t; cvta.to.shared.u64 t, %1; cvt.u32.u64 %0, t; }" : "=r"(a) : "l"(p));
    return a;
}

__device__ __forceinline__ void ldsm4(uint32_t addr, uint32_t* r) {
    asm volatile("ldmatrix.sync.aligned.m8n8.x4.shared.b16 {%0,%1,%2,%3}, [%4];"
                 : "=r"(r[0]), "=r"(r[1]), "=r"(r[2]), "=r"(r[3]) : "r"(addr));
}

__device__ __forceinline__ void mma16816(float* c, const uint32_t* a, uint32_t b0, uint32_t b1) {
    asm volatile("mma.sync.aligned.m16n8k16.row.col.f32.bf16.bf16.f32 "
                 "{%0,%1,%2,%3}, {%4,%5,%6,%7}, {%8,%9}, {%0,%1,%2,%3};"
                 : "+f"(c[0]), "+f"(c[1]), "+f"(c[2]), "+f"(c[3])
                 : "r"(a[0]), "r"(a[1]), "r"(a[2]), "r"(a[3]), "r"(b0), "r"(b1));
}

__device__ __forceinline__ void split_bf16(float v, __nv_bfloat16& h, __nv_bfloat16& l) {
    h = __float2bfloat16(v);
    l = __float2bfloat16(v - __bfloat162float(h));
}

// ---------------- weight prep ----------------
__global__ void prep_projw(const float* __restrict__ W, __nv_bfloat16* __restrict__ hi,
                           __nv_bfloat16* __restrict__ lo) {
    int i = blockIdx.x * 256 + threadIdx.x;
    if (i >= IND * 128) return;
    int k = i >> 7, n = i & 127;
    __nv_bfloat16 h, l;
    split_bf16(W[i], h, l);
    hi[n * IND + k] = h;
    lo[n * IND + k] = l;
}

__global__ void prep_layerw(const float* __restrict__ Wl, const float* __restrict__ bl,
                            const float* __restrict__ Wr) {
    int l = blockIdx.y;
    int i = blockIdx.x * 256 + threadIdx.x;
    if (i >= HH) return;
    int k = i >> 7, n = i & 127;
    __nv_bfloat16 h, lo;
    // paper concat GEMM: K [0:128)=0.5*Wl[l,0], [128:256)=0.5*Wl[l,1], [256:384)=0.5*(Wr0+Wr1)
    split_bf16(0.5f * Wl[(l * 3 + 0) * HH + i], h, lo);
    g_wLPh[l][n * 384 + k] = h;       g_wLPl[l][n * 384 + k] = lo;
    split_bf16(0.5f * Wl[(l * 3 + 1) * HH + i], h, lo);
    g_wLPh[l][n * 384 + 128 + k] = h; g_wLPl[l][n * 384 + 128 + k] = lo;
    split_bf16(0.5f * (Wr[(l * 3 + 0) * HH + i] + Wr[(l * 3 + 1) * HH + i]), h, lo);
    g_wLPh[l][n * 384 + 256 + k] = h; g_wLPl[l][n * 384 + 256 + k] = lo;
    // author concat GEMM: [0:128)=Wl[l,2], [128:256)=Wr[l,2]
    split_bf16(Wl[(l * 3 + 2) * HH + i], h, lo);
    g_wLAh[l][n * 256 + k] = h;       g_wLAl[l][n * 256 + k] = lo;
    split_bf16(Wr[(l * 3 + 2) * HH + i], h, lo);
    g_wLAh[l][n * 256 + 128 + k] = h; g_wLAl[l][n * 256 + 128 + k] = lo;
    if (blockIdx.x == 0 && i < H)
        g_bp[l * H + i] = 0.5f * (bl[(l * 3 + 0) * H + i] + bl[(l * 3 + 1) * H + i]);
}

// ---------------- CSR build ----------------
__global__ void zero_int(int* __restrict__ p, int n) {
    int i = blockIdx.x * blockDim.x + threadIdx.x;
    if (i < n) p[i] = 0;
}
__global__ void count_k(const int* __restrict__ dst, int* __restrict__ cnt, int n) {
    int i = blockIdx.x * blockDim.x + threadIdx.x;
    if (i < n) atomicAdd(&cnt[dst[i]], 1);
}
__global__ void scan_excl(const int* __restrict__ cnt, int* __restrict__ ptr, int n) {
    __shared__ int ss[1024];
    int tid = threadIdx.x;
    int C = (n + 1023) >> 10;
    int start = tid * C;
    int s = 0;
    for (int i = 0; i < C; i++) { int p = start + i; if (p < n) s += cnt[p]; }
    ss[tid] = s;
    __syncthreads();
    for (int off = 1; off < 1024; off <<= 1) {
        int v = (tid >= off) ? ss[tid - off] : 0;
        __syncthreads();
        ss[tid] += v;
        __syncthreads();
    }
    int run = (tid > 0) ? ss[tid - 1] : 0;
    for (int i = 0; i < C; i++) {
        int p = start + i;
        if (p <= n) { ptr[p] = run; if (p < n) run += cnt[p]; }
    }
}
__global__ void fill_k(const int* __restrict__ src, const int* __restrict__ dst,
                       const int* __restrict__ ptr, int* __restrict__ tmp,
                       int* __restrict__ cidx, int n) {
    int i = blockIdx.x * blockDim.x + threadIdx.x;
    if (i < n) {
        int d = dst[i];
        int p = atomicAdd(&tmp[d], 1);
        cidx[ptr[d] + p] = src[i];
    }
}

// ---------------- mean aggregation: one warp per destination node ----------------
__global__ void agg_mean(const float* __restrict__ feat, const int* __restrict__ ptr,
                         const int* __restrict__ idx, float* __restrict__ out, int n) {
    int w = (blockIdx.x * blockDim.x + threadIdx.x) >> 5;
    int lane = threadIdx.x & 31;
    if (w >= n) return;
    int beg = ptr[w], end = ptr[w + 1];
    float ax = 0.f, ay = 0.f, az = 0.f, aw = 0.f;
    int e = beg;
    for (; e + 4 <= end; e += 4) {
        int s0 = idx[e], s1 = idx[e + 1], s2 = idx[e + 2], s3 = idx[e + 3];
        float4 v0 = ((const float4*)(feat + (size_t)s0 * H))[lane];
        float4 v1 = ((const float4*)(feat + (size_t)s1 * H))[lane];
        float4 v2 = ((const float4*)(feat + (size_t)s2 * H))[lane];
        float4 v3 = ((const float4*)(feat + (size_t)s3 * H))[lane];
        ax += (v0.x + v1.x) + (v2.x + v3.x);
        ay += (v0.y + v1.y) + (v2.y + v3.y);
        az += (v0.z + v1.z) + (v2.z + v3.z);
        aw += (v0.w + v1.w) + (v2.w + v3.w);
    }
    for (; e < end; e++) {
        int s0 = idx[e];
        float4 v0 = ((const float4*)(feat + (size_t)s0 * H))[lane];
        ax += v0.x; ay += v0.y; az += v0.z; aw += v0.w;
    }
    int c = end - beg;
    float inv = 1.0f / (float)(c > 1 ? c : 1);
    float4 r;
    r.x = ax * inv; r.y = ay * inv; r.z = az * inv; r.w = aw * inv;
    ((float4*)(out + (size_t)w * H))[lane] = r;
}

// ---------------- warp-MMA bf16x2-split GEMM (ldmatrix + mma.sync) ----------------
// out[M,128] = EPI( concat(A0..A{NMAT-1})[M,KC] @ Wt^T + bias )
// Wt = [128 n][KC k] bf16 hi/lo, pre-transposed, scales folded.
// EPI 0: LayerNorm(lng,lnb)+ReLU; EPI 1: ReLU; EPI 2: ReLU += res.
// CTA: 128x128 tile, 8 warps (warp = 32m x 64n). K staged 64 wide; A split to
// bf16 hi/lo on the fly. 3 terms: Ah*Bh + Ah*Bl + Al*Bh (fp32 accum frags).
// smem: Ah 0 | Al 16K | Bh 32K | Bl 48K (rows 128B, unit-XOR swizzle u^=(r&7)).
#define SMEM_SZ 65536
template <int NMAT, int KC, int EPI>
__global__ __launch_bounds__(256, 2) void hgemm(
    const float* __restrict__ A0, const float* __restrict__ A1, const float* __restrict__ A2,
    const __nv_bfloat16* __restrict__ Bhi, const __nv_bfloat16* __restrict__ Blo,
    const float* __restrict__ bias, const float* __restrict__ lng, const float* __restrict__ lnb,
    const float* __restrict__ res, float* __restrict__ out, int M) {
    extern __shared__ char sm[];
    uint32_t sbase = s2u(sm);
    int t = threadIdx.x, lane = t & 31, wid = t >> 5;
    int wm = wid & 3, wn = wid >> 2;          // warp tile: rows 32*wm, cols 64*wn
    int row0 = blockIdx.x * 128;
    const int SEG = KC / NMAT;
    const float* Aall[3] = {A0, A1, A2};

    float acc[2][8][4];
    #pragma unroll
    for (int a = 0; a < 2; a++)
        #pragma unroll
        for (int b = 0; b < 8; b++)
            #pragma unroll
            for (int c = 0; c < 4; c++) acc[a][b][c] = 0.f;

    const int NI = KC / 64;
    for (int i = 0; i < NI; i++) {
        int k0 = i * 64;
        int mseg = k0 / SEG, kl = k0 - mseg * SEG;
        const float* A = Aall[mseg];
        // ---- stage A (fp32 -> bf16 hi/lo), 128 rows x 64 k ----
        #pragma unroll
        for (int it = 0; it < 4; it++) {
            int uid = t + 256 * it;
            int r = uid >> 3, u = uid & 7;
            int gr = row0 + r;
            float4 v0 = make_float4(0.f, 0.f, 0.f, 0.f), v1 = v0;
            if (gr < M) {
                const float* p = A + (size_t)gr * SEG + kl + 8 * u;
                v0 = *(const float4*)p;
                v1 = *(const float4*)(p + 4);
            }
            float f[8] = {v0.x, v0.y, v0.z, v0.w, v1.x, v1.y, v1.z, v1.w};
            unsigned ph[4], pl[4];
            #pragma unroll
            for (int j = 0; j < 4; j++) {
                __nv_bfloat16 h0, l0, h1, l1;
                split_bf16(f[2 * j], h0, l0);
                split_bf16(f[2 * j + 1], h1, l1);
                ph[j] = (unsigned)__bfloat16_as_ushort(h0) | ((unsigned)__bfloat16_as_ushort(h1) << 16);
                pl[j] = (unsigned)__bfloat16_as_ushort(l0) | ((unsigned)__bfloat16_as_ushort(l1) << 16);
            }
            uint32_t off = (uint32_t)(r * 128 + ((u ^ (r & 7)) << 4));
            *(uint4*)(sm + off)         = make_uint4(ph[0], ph[1], ph[2], ph[3]);
            *(uint4*)(sm + 16384 + off) = make_uint4(pl[0], pl[1], pl[2], pl[3]);
        }
        // ---- stage B (pre-split bf16), 128 n x 64 k ----
        #pragma unroll
        for (int it = 0; it < 4; it++) {
            int uid = t + 256 * it;
            int n = uid >> 3, u = uid & 7;
            size_t go = (size_t)n * KC + k0 + 8 * u;
            uint32_t off = (uint32_t)(n * 128 + ((u ^ (n & 7)) << 4));
            *(uint4*)(sm + 32768 + off) = *(const uint4*)(Bhi + go);
            *(uint4*)(sm + 49152 + off) = *(const uint4*)(Blo + go);
        }
        __syncthreads();
        // ---- compute: 4 k16 steps ----
        int e = lane & 7, q = lane >> 3;
        int qr = (q & 1) * 8 + e, qu = q >> 1;
        #pragma unroll
        for (int ks = 0; ks < 4; ks++) {
            uint32_t ah[2][4], al[2][4];
            #pragma unroll
            for (int mt = 0; mt < 2; mt++) {
                int r = wm * 32 + mt * 16 + qr;
                int u = 2 * ks + qu;
                uint32_t ad = sbase + (uint32_t)(r * 128 + ((u ^ (r & 7)) << 4));
                ldsm4(ad, ah[mt]);
                ldsm4(ad + 16384u, al[mt]);
            }
            #pragma unroll
            for (int nt2 = 0; nt2 < 4; nt2++) {
                int rn = wn * 64 + nt2 * 16 + qr;
                int u = 2 * ks + qu;
                uint32_t bd = sbase + (uint32_t)(rn * 128 + ((u ^ (rn & 7)) << 4));
                uint32_t bh[4], bl[4];
                ldsm4(bd + 32768u, bh);
                ldsm4(bd + 49152u, bl);
                #pragma unroll
                for (int mt = 0; mt < 2; mt++)
                    #pragma unroll
                    for (int s = 0; s < 2; s++) {
                        float* cc = acc[mt][2 * nt2 + s];
                        mma16816(cc, ah[mt], bh[s], bh[2 + s]);
                        mma16816(cc, ah[mt], bl[s], bl[2 + s]);
                        mma16816(cc, al[mt], bh[s], bh[2 + s]);
                    }
            }
        }
        __syncthreads();
    }

    // ---- epilogue ----
    int la = lane >> 2, lc = 2 * (lane & 3);
    float2 b2[8];
    #pragma unroll
    for (int nt = 0; nt < 8; nt++)
        b2[nt] = *(const float2*)(bias + wn * 64 + nt * 8 + lc);
    #pragma unroll
    for (int mt = 0; mt < 2; mt++)
        #pragma unroll
        for (int nt = 0; nt < 8; nt++) {
            acc[mt][nt][0] += b2[nt].x; acc[mt][nt][1] += b2[nt].y;
            acc[mt][nt][2] += b2[nt].x; acc[mt][nt][3] += b2[nt].y;
        }

    if (EPI == 0) {
        float* red = (float*)sm;    // [2 halves][128 rows][2] = 2KB (smem free now)
        float s1[2][2], s2[2][2];
        #pragma unroll
        for (int mt = 0; mt < 2; mt++)
            #pragma unroll
            for (int h = 0; h < 2; h++) {
                float a1 = 0.f, a2 = 0.f;
                #pragma unroll
                for (int nt = 0; nt < 8; nt++) {
                    float vx = acc[mt][nt][2 * h], vy = acc[mt][nt][2 * h + 1];
                    a1 += vx + vy;
                    a2 += vx * vx + vy * vy;
                }
                a1 += __shfl_xor_sync(0xffffffffu, a1, 1);
                a1 += __shfl_xor_sync(0xffffffffu, a1, 2);
                a2 += __shfl_xor_sync(0xffffffffu, a2, 1);
                a2 += __shfl_xor_sync(0xffffffffu, a2, 2);
                s1[mt][h] = a1; s2[mt][h] = a2;
            }
        if ((lane & 3) == 0) {
            #pragma unroll
            for (int mt = 0; mt < 2; mt++)
                #pragma unroll
                for (int h = 0; h < 2; h++) {
                    int rl = wm * 32 + mt * 16 + la + h * 8;
                    red[(wn * 128 + rl) * 2 + 0] = s1[mt][h];
                    red[(wn * 128 + rl) * 2 + 1] = s2[mt][h];
                }
        }
        __syncthreads();
        float2 lg2[8], lb2[8];
        #pragma unroll
        for (int nt = 0; nt < 8; nt++) {
            lg2[nt] = *(const float2*)(lng + wn * 64 + nt * 8 + lc);
            lb2[nt] = *(const float2*)(lnb + wn * 64 + nt * 8 + lc);
        }
        #pragma unroll
        for (int mt = 0; mt < 2; mt++)
            #pragma unroll
            for (int h = 0; h < 2; h++) {
                int rl = wm * 32 + mt * 16 + la + h * 8;
                float o1 = red[((1 - wn) * 128 + rl) * 2 + 0];
                float o2 = red[((1 - wn) * 128 + rl) * 2 + 1];
                float mu = (s1[mt][h] + o1) * (1.0f / 128.0f);
                float ex2 = (s2[mt][h] + o2) * (1.0f / 128.0f);
                float rstd = rsqrtf(fmaxf(ex2 - mu * mu, 0.f) + 1e-5f);
                #pragma unroll
                for (int nt = 0; nt < 8; nt++) {
                    float vx = acc[mt][nt][2 * h], vy = acc[mt][nt][2 * h + 1];
                    vx = fmaxf((vx - mu) * rstd * lg2[nt].x + lb2[nt].x, 0.f);
                    vy = fmaxf((vy - mu) * rstd * lg2[nt].y + lb2[nt].y, 0.f);
                    acc[mt][nt][2 * h] = vx; acc[mt][nt][2 * h + 1] = vy;
                }
            }
    } else {
        #pragma unroll
        for (int mt = 0; mt < 2; mt++)
            #pragma unroll
            for (int nt = 0; nt < 8; nt++)
                #pragma unroll
                for (int c = 0; c < 4; c++)
                    acc[mt][nt][c] = fmaxf(acc[mt][nt][c], 0.f);
    }

    #pragma unroll
    for (int mt = 0; mt < 2; mt++)
        #pragma unroll
        for (int h = 0; h < 2; h++) {
            int row = row0 + wm * 32 + mt * 16 + la + h * 8;
            if (row < M) {
                #pragma unroll
                for (int nt = 0; nt < 8; nt++) {
                    int col = wn * 64 + nt * 8 + lc;
                    float vx = acc[mt][nt][2 * h], vy = acc[mt][nt][2 * h + 1];
                    if (EPI == 2) {
                        float2 rv = *(const float2*)(res + (size_t)row * H + col);
                        vx += rv.x; vy += rv.y;
                    }
                    float2 o; o.x = vx; o.y = vy;
                    *(float2*)(out + (size_t)row * H + col) = o;
                }
            }
        }
}

// ---------------- launch ----------------
extern "C" void kernel_launch(void* const* d_in, const int* in_sizes, int n_in,
                              void* d_out, int out_size) {
    const float* x_paper   = (const float*)d_in[0];
    const float* x_author  = (const float*)d_in[1];
    const float* pw_paper  = (const float*)d_in[2];
    const float* pb_paper  = (const float*)d_in[3];
    const float* lng_paper = (const float*)d_in[4];
    const float* lnb_paper = (const float*)d_in[5];
    const float* pw_author  = (const float*)d_in[6];
    const float* pb_author  = (const float*)d_in[7];
    const float* lng_author = (const float*)d_in[8];
    const float* lnb_author = (const float*)d_in[9];
    const float* Wl = (const float*)d_in[10];
    const float* bl = (const float*)d_in[11];
    const float* Wr = (const float*)d_in[12];
    const int* cs = (const int*)d_in[13];
    const int* cd = (const int*)d_in[14];
    const int* ws = (const int*)d_in[15];
    const int* wd = (const int*)d_in[16];
    const int* rs = (const int*)d_in[17];
    const int* rd = (const int*)d_in[18];
    float* out = (float*)d_out;

    float *hp, *ha, *zp, *za, *aggc, *aggw, *aggr, *bp;
    __nv_bfloat16 *wPh, *wPl, *wAh, *wAl, *wLPh, *wLPl, *wLAh, *wLAl;
    int *cptr, *cidx, *wptr, *widx, *rptr, *ridx, *tmp;
    cudaGetSymbolAddress((void**)&hp, g_hp);
    cudaGetSymbolAddress((void**)&ha, g_ha);
    cudaGetSymbolAddress((void**)&zp, g_zp);
    cudaGetSymbolAddress((void**)&za, g_za);
    cudaGetSymbolAddress((void**)&aggc, g_aggc);
    cudaGetSymbolAddress((void**)&aggw, g_aggw);
    cudaGetSymbolAddress((void**)&aggr, g_aggr);
    cudaGetSymbolAddress((void**)&bp, g_bp);
    cudaGetSymbolAddress((void**)&wPh, g_wPh);
    cudaGetSymbolAddress((void**)&wPl, g_wPl);
    cudaGetSymbolAddress((void**)&wAh, g_wAh);
    cudaGetSymbolAddress((void**)&wAl, g_wAl);
    cudaGetSymbolAddress((void**)&wLPh, g_wLPh);
    cudaGetSymbolAddress((void**)&wLPl, g_wLPl);
    cudaGetSymbolAddress((void**)&wLAh, g_wLAh);
    cudaGetSymbolAddress((void**)&wLAl, g_wLAl);
    cudaGetSymbolAddress((void**)&cptr, g_cptr);
    cudaGetSymbolAddress((void**)&cidx, g_cidx);
    cudaGetSymbolAddress((void**)&wptr, g_wptr);
    cudaGetSymbolAddress((void**)&widx, g_widx);
    cudaGetSymbolAddress((void**)&rptr, g_rptr);
    cudaGetSymbolAddress((void**)&ridx, g_ridx);
    cudaGetSymbolAddress((void**)&tmp, g_tmp);

    cudaFuncSetAttribute(hgemm<1, IND, 0>, cudaFuncAttributeMaxDynamicSharedMemorySize, SMEM_SZ);
    cudaFuncSetAttribute(hgemm<3, 384, 1>, cudaFuncAttributeMaxDynamicSharedMemorySize, SMEM_SZ);
    cudaFuncSetAttribute(hgemm<2, 256, 1>, cudaFuncAttributeMaxDynamicSharedMemorySize, SMEM_SZ);
    cudaFuncSetAttribute(hgemm<3, 384, 2>, cudaFuncAttributeMaxDynamicSharedMemorySize, SMEM_SZ);
    cudaFuncSetAttribute(hgemm<2, 256, 2>, cudaFuncAttributeMaxDynamicSharedMemorySize, SMEM_SZ);

    // weight prep
    prep_projw<<<(IND * 128 + 255) / 256, 256>>>(pw_paper, wPh, wPl);
    prep_projw<<<(IND * 128 + 255) / 256, 256>>>(pw_author, wAh, wAl);
    {
        dim3 g((HH + 255) / 256, 2);
        prep_layerw<<<g, 256>>>(Wl, bl, Wr);
    }

    // projections: Linear -> LayerNorm -> ReLU
    hgemm<1, IND, 0><<<(N_P + 127) / 128, 256, SMEM_SZ>>>(
        x_paper, nullptr, nullptr, wPh, wPl,
        pb_paper, lng_paper, lnb_paper, nullptr, hp, N_P);
    hgemm<1, IND, 0><<<(N_A + 127) / 128, 256, SMEM_SZ>>>(
        x_author, nullptr, nullptr, wAh, wAl,
        pb_author, lng_author, lnb_author, nullptr, ha, N_A);

    // CSR build (shared by both layers)
    auto build = [&](const int* s, const int* d, int nn, int ne, int* ptr, int* ci) {
        zero_int<<<(nn + 255) / 256, 256>>>(tmp, nn);
        count_k<<<(ne + 255) / 256, 256>>>(d, tmp, ne);
        scan_excl<<<1, 1024>>>(tmp, ptr, nn);
        zero_int<<<(nn + 255) / 256, 256>>>(tmp, nn);
        fill_k<<<(ne + 255) / 256, 256>>>(s, d, ptr, tmp, ci, ne);
    };
    build(cs, cd, N_P, E_C, cptr, cidx);
    build(ws, wd, N_P, E_W, wptr, widx);
    build(rs, rd, N_A, E_W, rptr, ridx);

    // ---- layer 1 ----
    agg_mean<<<(N_P + 7) / 8, 256>>>(hp, cptr, cidx, aggc, N_P);
    agg_mean<<<(N_P + 7) / 8, 256>>>(ha, wptr, widx, aggw, N_P);
    agg_mean<<<(N_A + 7) / 8, 256>>>(hp, rptr, ridx, aggr, N_A);
    hgemm<3, 384, 1><<<(N_P + 127) / 128, 256, SMEM_SZ>>>(
        aggc, aggw, hp, wLPh, wLPl,
        bp, nullptr, nullptr, nullptr, zp, N_P);
    hgemm<2, 256, 1><<<(N_A + 127) / 128, 256, SMEM_SZ>>>(
        aggr, ha, nullptr, wLAh, wLAl,
        bl + 2 * H, nullptr, nullptr, nullptr, za, N_A);

    // ---- layer 2 (residual fused, writes d_out) ----
    agg_mean<<<(N_P + 7) / 8, 256>>>(zp, cptr, cidx, aggc, N_P);
    agg_mean<<<(N_P + 7) / 8, 256>>>(za, wptr, widx, aggw, N_P);
    agg_mean<<<(N_A + 7) / 8, 256>>>(zp, rptr, ridx, aggr, N_A);
    hgemm<3, 384, 2><<<(N_P + 127) / 128, 256, SMEM_SZ>>>(
        aggc, aggw, zp, wLPh + (size_t)128 * 384, wLPl + (size_t)128 * 384,
        bp + H, nullptr, nullptr, hp, out, N_P);
    hgemm<2, 256, 2><<<(N_A + 127) / 128, 256, SMEM_SZ>>>(
        aggr, za, nullptr, wLAh + (size_t)128 * 256, wLAl + (size_t)128 * 256,
        bl + 5 * H, nullptr, nullptr, ha, out + (size_t)N_P * H, N_A);

    (void)in_sizes; (void)n_in; (void)out_size;
}

// round 10
// speedup vs baseline: 1.9993x; 1.0765x over previous
#include <cuda_runtime.h>
#include <cuda_bf16.h>
#include <cstdint>

#define N_P 100000
#define N_A 50000
#define E_C 1600000
#define E_W 800000
#define IND 768
#define H   128
#define HH  (128*128)

// ---------------- scratch (device globals; no allocation) ----------------
__device__ float g_hp[(size_t)N_P * H];
__device__ float g_ha[(size_t)N_A * H];
__device__ float g_zp[(size_t)N_P * H];
__device__ float g_za[(size_t)N_A * H];
__device__ float g_aggc[(size_t)N_P * H];
__device__ float g_aggw[(size_t)N_P * H];
__device__ float g_aggr[(size_t)N_A * H];
__device__ float g_bp[2 * H];    // 0.5*(bl[l,0]+bl[l,1])
// transposed + bf16-split + k-permuted weights: [N=128 rows][K cols]
__device__ __align__(16) __nv_bfloat16 g_wPh[128 * IND], g_wPl[128 * IND];   // paper proj
__device__ __align__(16) __nv_bfloat16 g_wAh[128 * IND], g_wAl[128 * IND];   // author proj
__device__ __align__(16) __nv_bfloat16 g_wLPh[2][128 * 384], g_wLPl[2][128 * 384]; // paper layer (K=384)
__device__ __align__(16) __nv_bfloat16 g_wLAh[2][128 * 256], g_wLAl[2][128 * 256]; // author layer (K=256)
__device__ int g_cptr[N_P + 1], g_cidx[E_C];
__device__ int g_wptr[N_P + 1], g_widx[E_W];
__device__ int g_rptr[N_A + 1], g_ridx[E_W];
__device__ int g_tmp[N_P + 1];

// ---------------- helpers ----------------
__device__ __forceinline__ uint32_t s2u(const void* p) {
    uint32_t a;
    asm("{ .reg .u64 t; cvta.to.shared.u64 t, %1; cvt.u32.u64 %0, t; }" : "=r"(a) : "l"(p));
    return a;
}

__device__ __forceinline__ void ldsm4(uint32_t addr, uint32_t* r) {
    asm volatile("ldmatrix.sync.aligned.m8n8.x4.shared.b16 {%0,%1,%2,%3}, [%4];"
                 : "=r"(r[0]), "=r"(r[1]), "=r"(r[2]), "=r"(r[3]) : "r"(addr));
}

__device__ __forceinline__ void mma16816(float* c, const uint32_t* a, uint32_t b0, uint32_t b1) {
    asm volatile("mma.sync.aligned.m16n8k16.row.col.f32.bf16.bf16.f32 "
                 "{%0,%1,%2,%3}, {%4,%5,%6,%7}, {%8,%9}, {%0,%1,%2,%3};"
                 : "+f"(c[0]), "+f"(c[1]), "+f"(c[2]), "+f"(c[3])
                 : "r"(a[0]), "r"(a[1]), "r"(a[2]), "r"(a[3]), "r"(b0), "r"(b1));
}

__device__ __forceinline__ void cpa16(uint32_t dst, const void* src, int sz) {
    asm volatile("cp.async.cg.shared.global [%0], [%1], 16, %2;"
                 :: "r"(dst), "l"(src), "r"(sz));
}
#define CP_COMMIT() asm volatile("cp.async.commit_group;" ::: "memory")

__device__ __forceinline__ uint32_t prmt7632(uint32_t a, uint32_t b) {
    uint32_t d; asm("prmt.b32 %0, %1, %2, 0x7632;" : "=r"(d) : "r"(a), "r"(b)); return d;
}
__device__ __forceinline__ float lopart(uint32_t xb) {
    float x = __uint_as_float(xb);
    return x - __uint_as_float(xb & 0xffff0000u);
}
__device__ __forceinline__ uint32_t bf16x2pack(float hi, float lo) {
    uint32_t d; asm("cvt.rn.bf16x2.f32 %0, %1, %2;" : "=r"(d) : "f"(hi), "f"(lo)); return d;
}

__device__ __forceinline__ void split_bf16(float v, __nv_bfloat16& h, __nv_bfloat16& l) {
    h = __float2bfloat16(v);
    l = __float2bfloat16(v - __bfloat162float(h));
}

// k-permutation within each 16-block: storage position for original k
__host__ __device__ __forceinline__ int invp(int k) {
    return (k & 8) | ((k & 3) << 1) | ((k >> 2) & 1);
}
__device__ __forceinline__ int permk(int k) {     // full-index version
    return (k & ~15) | invp(k & 15);
}

// ---------------- weight prep (transpose + split + k-permute) ----------------
__global__ void prep_projw(const float* __restrict__ W, __nv_bfloat16* __restrict__ hi,
                           __nv_bfloat16* __restrict__ lo) {
    int i = blockIdx.x * 256 + threadIdx.x;
    if (i >= IND * 128) return;
    int k = i >> 7, n = i & 127;
    __nv_bfloat16 h, l;
    split_bf16(W[i], h, l);
    int kk = permk(k);
    hi[n * IND + kk] = h;
    lo[n * IND + kk] = l;
}

__global__ void prep_layerw(const float* __restrict__ Wl, const float* __restrict__ bl,
                            const float* __restrict__ Wr) {
    int l = blockIdx.y;
    int i = blockIdx.x * 256 + threadIdx.x;
    if (i >= HH) return;
    int k = i >> 7, n = i & 127;
    int kk = permk(k);
    __nv_bfloat16 h, lo;
    // paper concat GEMM: K [0:128)=0.5*Wl[l,0], [128:256)=0.5*Wl[l,1], [256:384)=0.5*(Wr0+Wr1)
    split_bf16(0.5f * Wl[(l * 3 + 0) * HH + i], h, lo);
    g_wLPh[l][n * 384 + kk] = h;       g_wLPl[l][n * 384 + kk] = lo;
    split_bf16(0.5f * Wl[(l * 3 + 1) * HH + i], h, lo);
    g_wLPh[l][n * 384 + 128 + kk] = h; g_wLPl[l][n * 384 + 128 + kk] = lo;
    split_bf16(0.5f * (Wr[(l * 3 + 0) * HH + i] + Wr[(l * 3 + 1) * HH + i]), h, lo);
    g_wLPh[l][n * 384 + 256 + kk] = h; g_wLPl[l][n * 384 + 256 + kk] = lo;
    // author concat GEMM: [0:128)=Wl[l,2], [128:256)=Wr[l,2]
    split_bf16(Wl[(l * 3 + 2) * HH + i], h, lo);
    g_wLAh[l][n * 256 + kk] = h;       g_wLAl[l][n * 256 + kk] = lo;
    split_bf16(Wr[(l * 3 + 2) * HH + i], h, lo);
    g_wLAh[l][n * 256 + 128 + kk] = h; g_wLAl[l][n * 256 + 128 + kk] = lo;
    if (blockIdx.x == 0 && i < H)
        g_bp[l * H + i] = 0.5f * (bl[(l * 3 + 0) * H + i] + bl[(l * 3 + 1) * H + i]);
}

// ---------------- CSR build ----------------
__global__ void zero_int(int* __restrict__ p, int n) {
    int i = blockIdx.x * blockDim.x + threadIdx.x;
    if (i < n) p[i] = 0;
}
__global__ void count_k(const int* __restrict__ dst, int* __restrict__ cnt, int n) {
    int i = blockIdx.x * blockDim.x + threadIdx.x;
    if (i < n) atomicAdd(&cnt[dst[i]], 1);
}
__global__ void scan_excl(const int* __restrict__ cnt, int* __restrict__ ptr, int n) {
    __shared__ int ss[1024];
    int tid = threadIdx.x;
    int C = (n + 1023) >> 10;
    int start = tid * C;
    int s = 0;
    for (int i = 0; i < C; i++) { int p = start + i; if (p < n) s += cnt[p]; }
    ss[tid] = s;
    __syncthreads();
    for (int off = 1; off < 1024; off <<= 1) {
        int v = (tid >= off) ? ss[tid - off] : 0;
        __syncthreads();
        ss[tid] += v;
        __syncthreads();
    }
    int run = (tid > 0) ? ss[tid - 1] : 0;
    for (int i = 0; i < C; i++) {
        int p = start + i;
        if (p <= n) { ptr[p] = run; if (p < n) run += cnt[p]; }
    }
}
__global__ void fill_k(const int* __restrict__ src, const int* __restrict__ dst,
                       const int* __restrict__ ptr, int* __restrict__ tmp,
                       int* __restrict__ cidx, int n) {
    int i = blockIdx.x * blockDim.x + threadIdx.x;
    if (i < n) {
        int d = dst[i];
        int p = atomicAdd(&tmp[d], 1);
        cidx[ptr[d] + p] = src[i];
    }
}

// ---------------- mean aggregation: one warp per destination node ----------------
__global__ void agg_mean(const float* __restrict__ feat, const int* __restrict__ ptr,
                         const int* __restrict__ idx, float* __restrict__ out, int n) {
    int w = (blockIdx.x * blockDim.x + threadIdx.x) >> 5;
    int lane = threadIdx.x & 31;
    if (w >= n) return;
    int beg = ptr[w], end = ptr[w + 1];
    float ax = 0.f, ay = 0.f, az = 0.f, aw = 0.f;
    int e = beg;
    for (; e + 4 <= end; e += 4) {
        int s0 = idx[e], s1 = idx[e + 1], s2 = idx[e + 2], s3 = idx[e + 3];
        float4 v0 = ((const float4*)(feat + (size_t)s0 * H))[lane];
        float4 v1 = ((const float4*)(feat + (size_t)s1 * H))[lane];
        float4 v2 = ((const float4*)(feat + (size_t)s2 * H))[lane];
        float4 v3 = ((const float4*)(feat + (size_t)s3 * H))[lane];
        ax += (v0.x + v1.x) + (v2.x + v3.x);
        ay += (v0.y + v1.y) + (v2.y + v3.y);
        az += (v0.z + v1.z) + (v2.z + v3.z);
        aw += (v0.w + v1.w) + (v2.w + v3.w);
    }
    for (; e < end; e++) {
        int s0 = idx[e];
        float4 v0 = ((const float4*)(feat + (size_t)s0 * H))[lane];
        ax += v0.x; ay += v0.y; az += v0.z; aw += v0.w;
    }
    int c = end - beg;
    float inv = 1.0f / (float)(c > 1 ? c : 1);
    float4 r;
    r.x = ax * inv; r.y = ay * inv; r.z = az * inv; r.w = aw * inv;
    ((float4*)(out + (size_t)w * H))[lane] = r;
}

// ---------------- async pipelined warp-MMA GEMM (cp.async + ldmatrix-on-fp32) ----------------
// out[M,128] = EPI( concat(A0..A{NMAT-1})[M,KC] @ Wt^T + bias )
// Wt = [128 n][KC k] bf16 hi/lo, pre-transposed, k-permuted (invp), scales folded.
// A stays fp32 in gmem; staged raw via cp.async; the bf16 hi/lo split happens in the
// compute phase via ldmatrix over fp32 + PRMT/CVT (k-pairing matches the B permutation).
// EPI 0: LayerNorm(lng,lnb)+ReLU; EPI 1: ReLU; EPI 2: ReLU += res.
// CTA 128x128 tile, 8 warps (32m x 64n each). KT=32 chunks, double-buffered.
// smem: Af32 2x16K @0 | Bh 2x8K @32768 | Bl 2x8K @49152  (total 64KB)
#define SMEM_SZ 65536
template <int NMAT, int KC, int EPI>
__global__ __launch_bounds__(256, 2) void pgemm(
    const float* __restrict__ A0, const float* __restrict__ A1, const float* __restrict__ A2,
    const __nv_bfloat16* __restrict__ Bhi, const __nv_bfloat16* __restrict__ Blo,
    const float* __restrict__ bias, const float* __restrict__ lng, const float* __restrict__ lnb,
    const float* __restrict__ res, float* __restrict__ out, int M) {
    extern __shared__ char sm[];
    uint32_t sbase = s2u(sm);
    int t = threadIdx.x, lane = t & 31, wid = t >> 5;
    int wm = wid & 3, wn = wid >> 2;          // warp tile: rows 32*wm, cols 64*wn
    int row0 = blockIdx.x * 128;
    const int SEG = KC / NMAT;
    const int NI = KC / 32;
    const float* Aall[3] = {A0, A1, A2};

    int q = lane >> 3, e = lane & 7;          // ldmatrix address lanes

    float acc[2][8][4];
    #pragma unroll
    for (int a = 0; a < 2; a++)
        #pragma unroll
        for (int b = 0; b < 8; b++)
            #pragma unroll
            for (int c = 0; c < 4; c++) acc[a][b][c] = 0.f;

    // ---- staging (pure cp.async) ----
    auto stage = [&](int i) {
        int b = i & 1;
        int k0 = i * 32;
        int mseg = k0 / SEG, kl = k0 - mseg * SEG;
        const float* A = Aall[mseg];
        #pragma unroll
        for (int it = 0; it < 4; it++) {
            int uid = t + 256 * it;
            int r = uid >> 3, u = uid & 7;
            int gr = row0 + r;
            int ok = (gr < M);
            const float* src = A + (size_t)(ok ? gr : 0) * SEG + kl + 4 * u;
            uint32_t dst = sbase + b * 16384 + (uint32_t)(r * 128 + ((u ^ (r & 7)) << 4));
            cpa16(dst, src, ok ? 16 : 0);
        }
        #pragma unroll
        for (int it = 0; it < 2; it++) {
            int uid = t + 256 * it;
            int n = uid >> 2, v = uid & 3;
            size_t go = (size_t)n * KC + k0 + 8 * v;
            uint32_t off = (uint32_t)(n * 64 + ((v ^ ((n >> 1) & 3)) << 4));
            cpa16(sbase + 32768 + b * 8192 + off, Bhi + go, 16);
            cpa16(sbase + 49152 + b * 8192 + off, Blo + go, 16);
        }
        CP_COMMIT();
    };

    stage(0);
    for (int i = 0; i < NI; i++) {
        if (i + 1 < NI) {
            stage(i + 1);
            asm volatile("cp.async.wait_group 1;" ::: "memory");
        } else {
            asm volatile("cp.async.wait_group 0;" ::: "memory");
        }
        __syncthreads();
        int b = i & 1;
        uint32_t aB = sbase + b * 16384;
        uint32_t bhB = sbase + 32768 + b * 8192;
        uint32_t blB = sbase + 49152 + b * 8192;
        #pragma unroll
        for (int ks = 0; ks < 2; ks++) {
            uint32_t AH[2][4], AL[2][4];
            #pragma unroll
            for (int mt = 0; mt < 2; mt++) {
                int arow = wm * 32 + mt * 16 + (q & 1) * 8 + e;
                uint32_t ro = (uint32_t)(arow * 128);
                int u1 = 4 * ks + (q >> 1);
                int u2 = u1 + 2;
                uint32_t x[8];
                ldsm4(aB + ro + (uint32_t)((u1 ^ (arow & 7)) << 4), x);
                ldsm4(aB + ro + (uint32_t)((u2 ^ (arow & 7)) << 4), x + 4);
                AH[mt][0] = prmt7632(x[0], x[2]);
                AH[mt][1] = prmt7632(x[1], x[3]);
                AH[mt][2] = prmt7632(x[4], x[6]);
                AH[mt][3] = prmt7632(x[5], x[7]);
                AL[mt][0] = bf16x2pack(lopart(x[2]), lopart(x[0]));
                AL[mt][1] = bf16x2pack(lopart(x[3]), lopart(x[1]));
                AL[mt][2] = bf16x2pack(lopart(x[6]), lopart(x[4]));
                AL[mt][3] = bf16x2pack(lopart(x[7]), lopart(x[5]));
            }
            #pragma unroll
            for (int nt2 = 0; nt2 < 4; nt2++) {
                int brow = wn * 64 + nt2 * 16 + (q & 1) * 8 + e;
                int v = 2 * ks + (q >> 1);
                uint32_t bo = (uint32_t)(brow * 64 + ((v ^ ((brow >> 1) & 3)) << 4));
                uint32_t bh[4], bl[4];
                ldsm4(bhB + bo, bh);
                ldsm4(blB + bo, bl);
                #pragma unroll
                for (int mt = 0; mt < 2; mt++)
                    #pragma unroll
                    for (int s = 0; s < 2; s++) {
                        float* cc = acc[mt][2 * nt2 + s];
                        mma16816(cc, AH[mt], bh[s], bh[2 + s]);
                        mma16816(cc, AH[mt], bl[s], bl[2 + s]);
                        mma16816(cc, AL[mt], bh[s], bh[2 + s]);
                    }
            }
        }
        __syncthreads();
    }

    // ---- epilogue ----
    int la = lane >> 2, lc = 2 * (lane & 3);
    float2 b2[8];
    #pragma unroll
    for (int nt = 0; nt < 8; nt++)
        b2[nt] = *(const float2*)(bias + wn * 64 + nt * 8 + lc);
    #pragma unroll
    for (int mt = 0; mt < 2; mt++)
        #pragma unroll
        for (int nt = 0; nt < 8; nt++) {
            acc[mt][nt][0] += b2[nt].x; acc[mt][nt][1] += b2[nt].y;
            acc[mt][nt][2] += b2[nt].x; acc[mt][nt][3] += b2[nt].y;
        }

    if (EPI == 0) {
        float* red = (float*)sm;    // smem free now
        float s1[2][2], s2[2][2];
        #pragma unroll
        for (int mt = 0; mt < 2; mt++)
            #pragma unroll
            for (int h = 0; h < 2; h++) {
                float a1 = 0.f, a2 = 0.f;
                #pragma unroll
                for (int nt = 0; nt < 8; nt++) {
                    float vx = acc[mt][nt][2 * h], vy = acc[mt][nt][2 * h + 1];
                    a1 += vx + vy;
                    a2 += vx * vx + vy * vy;
                }
                a1 += __shfl_xor_sync(0xffffffffu, a1, 1);
                a1 += __shfl_xor_sync(0xffffffffu, a1, 2);
                a2 += __shfl_xor_sync(0xffffffffu, a2, 1);
                a2 += __shfl_xor_sync(0xffffffffu, a2, 2);
                s1[mt][h] = a1; s2[mt][h] = a2;
            }
        if ((lane & 3) == 0) {
            #pragma unroll
            for (int mt = 0; mt < 2; mt++)
                #pragma unroll
                for (int h = 0; h < 2; h++) {
                    int rl = wm * 32 + mt * 16 + la + h * 8;
                    red[(wn * 128 + rl) * 2 + 0] = s1[mt][h];
                    red[(wn * 128 + rl) * 2 + 1] = s2[mt][h];
                }
        }
        __syncthreads();
        float2 lg2[8], lb2[8];
        #pragma unroll
        for (int nt = 0; nt < 8; nt++) {
            lg2[nt] = *(const float2*)(lng + wn * 64 + nt * 8 + lc);
            lb2[nt] = *(const float2*)(lnb + wn * 64 + nt * 8 + lc);
        }
        #pragma unroll
        for (int mt = 0; mt < 2; mt++)
            #pragma unroll
            for (int h = 0; h < 2; h++) {
                int rl = wm * 32 + mt * 16 + la + h * 8;
                float o1 = red[((1 - wn) * 128 + rl) * 2 + 0];
                float o2 = red[((1 - wn) * 128 + rl) * 2 + 1];
                float mu = (s1[mt][h] + o1) * (1.0f / 128.0f);
                float ex2 = (s2[mt][h] + o2) * (1.0f / 128.0f);
                float rstd = rsqrtf(fmaxf(ex2 - mu * mu, 0.f) + 1e-5f);
                #pragma unroll
                for (int nt = 0; nt < 8; nt++) {
                    float vx = acc[mt][nt][2 * h], vy = acc[mt][nt][2 * h + 1];
                    vx = fmaxf((vx - mu) * rstd * lg2[nt].x + lb2[nt].x, 0.f);
                    vy = fmaxf((vy - mu) * rstd * lg2[nt].y + lb2[nt].y, 0.f);
                    acc[mt][nt][2 * h] = vx; acc[mt][nt][2 * h + 1] = vy;
                }
            }
    } else {
        #pragma unroll
        for (int mt = 0; mt < 2; mt++)
            #pragma unroll
            for (int nt = 0; nt < 8; nt++)
                #pragma unroll
                for (int c = 0; c < 4; c++)
                    acc[mt][nt][c] = fmaxf(acc[mt][nt][c], 0.f);
    }

    #pragma unroll
    for (int mt = 0; mt < 2; mt++)
        #pragma unroll
        for (int h = 0; h < 2; h++) {
            int row = row0 + wm * 32 + mt * 16 + la + h * 8;
            if (row < M) {
                #pragma unroll
                for (int nt = 0; nt < 8; nt++) {
                    int col = wn * 64 + nt * 8 + lc;
                    float vx = acc[mt][nt][2 * h], vy = acc[mt][nt][2 * h + 1];
                    if (EPI == 2) {
                        float2 rv = *(const float2*)(res + (size_t)row * H + col);
                        vx += rv.x; vy += rv.y;
                    }
                    float2 o; o.x = vx; o.y = vy;
                    *(float2*)(out + (size_t)row * H + col) = o;
                }
            }
        }
}

// ---------------- launch ----------------
extern "C" void kernel_launch(void* const* d_in, const int* in_sizes, int n_in,
                              void* d_out, int out_size) {
    const float* x_paper   = (const float*)d_in[0];
    const float* x_author  = (const float*)d_in[1];
    const float* pw_paper  = (const float*)d_in[2];
    const float* pb_paper  = (const float*)d_in[3];
    const float* lng_paper = (const float*)d_in[4];
    const float* lnb_paper = (const float*)d_in[5];
    const float* pw_author  = (const float*)d_in[6];
    const float* pb_author  = (const float*)d_in[7];
    const float* lng_author = (const float*)d_in[8];
    const float* lnb_author = (const float*)d_in[9];
    const float* Wl = (const float*)d_in[10];
    const float* bl = (const float*)d_in[11];
    const float* Wr = (const float*)d_in[12];
    const int* cs = (const int*)d_in[13];
    const int* cd = (const int*)d_in[14];
    const int* ws = (const int*)d_in[15];
    const int* wd = (const int*)d_in[16];
    const int* rs = (const int*)d_in[17];
    const int* rd = (const int*)d_in[18];
    float* out = (float*)d_out;

    float *hp, *ha, *zp, *za, *aggc, *aggw, *aggr, *bp;
    __nv_bfloat16 *wPh, *wPl, *wAh, *wAl, *wLPh, *wLPl, *wLAh, *wLAl;
    int *cptr, *cidx, *wptr, *widx, *rptr, *ridx, *tmp;
    cudaGetSymbolAddress((void**)&hp, g_hp);
    cudaGetSymbolAddress((void**)&ha, g_ha);
    cudaGetSymbolAddress((void**)&zp, g_zp);
    cudaGetSymbolAddress((void**)&za, g_za);
    cudaGetSymbolAddress((void**)&aggc, g_aggc);
    cudaGetSymbolAddress((void**)&aggw, g_aggw);
    cudaGetSymbolAddress((void**)&aggr, g_aggr);
    cudaGetSymbolAddress((void**)&bp, g_bp);
    cudaGetSymbolAddress((void**)&wPh, g_wPh);
    cudaGetSymbolAddress((void**)&wPl, g_wPl);
    cudaGetSymbolAddress((void**)&wAh, g_wAh);
    cudaGetSymbolAddress((void**)&wAl, g_wAl);
    cudaGetSymbolAddress((void**)&wLPh, g_wLPh);
    cudaGetSymbolAddress((void**)&wLPl, g_wLPl);
    cudaGetSymbolAddress((void**)&wLAh, g_wLAh);
    cudaGetSymbolAddress((void**)&wLAl, g_wLAl);
    cudaGetSymbolAddress((void**)&cptr, g_cptr);
    cudaGetSymbolAddress((void**)&cidx, g_cidx);
    cudaGetSymbolAddress((void**)&wptr, g_wptr);
    cudaGetSymbolAddress((void**)&widx, g_widx);
    cudaGetSymbolAddress((void**)&rptr, g_rptr);
    cudaGetSymbolAddress((void**)&ridx, g_ridx);
    cudaGetSymbolAddress((void**)&tmp, g_tmp);

    cudaFuncSetAttribute(pgemm<1, IND, 0>, cudaFuncAttributeMaxDynamicSharedMemorySize, SMEM_SZ);
    cudaFuncSetAttribute(pgemm<3, 384, 1>, cudaFuncAttributeMaxDynamicSharedMemorySize, SMEM_SZ);
    cudaFuncSetAttribute(pgemm<2, 256, 1>, cudaFuncAttributeMaxDynamicSharedMemorySize, SMEM_SZ);
    cudaFuncSetAttribute(pgemm<3, 384, 2>, cudaFuncAttributeMaxDynamicSharedMemorySize, SMEM_SZ);
    cudaFuncSetAttribute(pgemm<2, 256, 2>, cudaFuncAttributeMaxDynamicSharedMemorySize, SMEM_SZ);

    // weight prep
    prep_projw<<<(IND * 128 + 255) / 256, 256>>>(pw_paper, wPh, wPl);
    prep_projw<<<(IND * 128 + 255) / 256, 256>>>(pw_author, wAh, wAl);
    {
        dim3 g((HH + 255) / 256, 2);
        prep_layerw<<<g, 256>>>(Wl, bl, Wr);
    }

    // projections: Linear -> LayerNorm -> ReLU
    pgemm<1, IND, 0><<<(N_P + 127) / 128, 256, SMEM_SZ>>>(
        x_paper, nullptr, nullptr, wPh, wPl,
        pb_paper, lng_paper, lnb_paper, nullptr, hp, N_P);
    pgemm<1, IND, 0><<<(N_A + 127) / 128, 256, SMEM_SZ>>>(
        x_author, nullptr, nullptr, wAh, wAl,
        pb_author, lng_author, lnb_author, nullptr, ha, N_A);

    // CSR build (shared by both layers)
    auto build = [&](const int* s, const int* d, int nn, int ne, int* ptr, int* ci) {
        zero_int<<<(nn + 255) / 256, 256>>>(tmp, nn);
        count_k<<<(ne + 255) / 256, 256>>>(d, tmp, ne);
        scan_excl<<<1, 1024>>>(tmp, ptr, nn);
        zero_int<<<(nn + 255) / 256, 256>>>(tmp, nn);
        fill_k<<<(ne + 255) / 256, 256>>>(s, d, ptr, tmp, ci, ne);
    };
    build(cs, cd, N_P, E_C, cptr, cidx);
    build(ws, wd, N_P, E_W, wptr, widx);
    build(rs, rd, N_A, E_W, rptr, ridx);

    // ---- layer 1 ----
    agg_mean<<<(N_P + 7) / 8, 256>>>(hp, cptr, cidx, aggc, N_P);
    agg_mean<<<(N_P + 7) / 8, 256>>>(ha, wptr, widx, aggw, N_P);
    agg_mean<<<(N_A + 7) / 8, 256>>>(hp, rptr, ridx, aggr, N_A);
    pgemm<3, 384, 1><<<(N_P + 127) / 128, 256, SMEM_SZ>>>(
        aggc, aggw, hp, wLPh, wLPl,
        bp, nullptr, nullptr, nullptr, zp, N_P);
    pgemm<2, 256, 1><<<(N_A + 127) / 128, 256, SMEM_SZ>>>(
        aggr, ha, nullptr, wLAh, wLAl,
        bl + 2 * H, nullptr, nullptr, nullptr, za, N_A);

    // ---- layer 2 (residual fused, writes d_out) ----
    agg_mean<<<(N_P + 7) / 8, 256>>>(zp, cptr, cidx, aggc, N_P);
    agg_mean<<<(N_P + 7) / 8, 256>>>(za, wptr, widx, aggw, N_P);
    agg_mean<<<(N_A + 7) / 8, 256>>>(zp, rptr, ridx, aggr, N_A);
    pgemm<3, 384, 2><<<(N_P + 127) / 128, 256, SMEM_SZ>>>(
        aggc, aggw, zp, wLPh + (size_t)128 * 384, wLPl + (size_t)128 * 384,
        bp + H, nullptr, nullptr, hp, out, N_P);
    pgemm<2, 256, 2><<<(N_A + 127) / 128, 256, SMEM_SZ>>>(
        aggr, za, nullptr, wLAh + (size_t)128 * 256, wLAl + (size_t)128 * 256,
        bl + 5 * H, nullptr, nullptr, ha, out + (size_t)N_P * H, N_A);

    (void)in_sizes; (void)n_in; (void)out_size;
}